// round 6
// baseline (speedup 1.0000x reference)
#include <cuda_runtime.h>
#include <cuda_bf16.h>
#include <cstdint>

// ---------------------------------------------------------------------------
// AdaConv fused kernel set (round 5).
// Shapes: N=8, CH=512, SD=512, H=W=128, NG=64 groups, CIG=8, 3x3 kernels.
// Launch order: prep1, heads(prep2+dw), stats, conv  -> conv is launch #4
// (ncu -s 5 -c 1 captures the 4th launch of the sequence).
// ---------------------------------------------------------------------------

typedef unsigned long long ull;

__device__ __forceinline__ ull pack2(float lo, float hi) {
    ull r;
    asm("mov.b64 %0, {%1, %2};" : "=l"(r) : "f"(lo), "f"(hi));
    return r;
}
__device__ __forceinline__ void unpack2(ull v, float& lo, float& hi) {
    asm("mov.b64 {%0, %1}, %2;" : "=f"(lo), "=f"(hi) : "l"(v));
}
__device__ __forceinline__ ull fma2(ull a, ull b, ull c) {
    ull d;
    asm("fma.rn.f32x2 %0, %1, %2, %3;" : "=l"(d) : "l"(a), "l"(b), "l"(c));
    return d;
}

// ------------------------- scratch (device globals) ------------------------
__device__ float g_colT[8 * 9 * 2048];   // im2col of style: [n][t][k]
__device__ float g_spool[8 * 512];       // avg-pooled style
__device__ float g_dw[8 * 4096 * 9];     // depthwise kernels [n][oc][t]
__device__ float g_pwkn[8 * 4096];       // pointwise kernels [n][c*8+j]
__device__ float g_pwbias[8 * 512];      // pointwise bias
__device__ float g_mean[8 * 512];
__device__ float g_rstd[8 * 512];

// ------------------------- K1: im2col + avg pool ---------------------------
__global__ void k_prep1(const float* __restrict__ style) {
    int idx = blockIdx.x * blockDim.x + threadIdx.x;
    const int COLT = 8 * 9 * 2048;
    if (idx < COLT) {
        int n = idx / (9 * 2048);
        int r = idx % (9 * 2048);
        int t = r / 2048;
        int k = r % 2048;
        int c = k >> 2, dy = (k >> 1) & 1, dx = k & 1;
        int ty = t / 3, tx = t % 3;
        g_colT[idx] = style[((n * 512 + c) * 4 + (ty + dy)) * 4 + (tx + dx)];
    } else if (idx < COLT + 4096) {
        int j = idx - COLT;
        const float* p = style + (size_t)j * 16;
        float s = 0.f;
#pragma unroll
        for (int q = 0; q < 16; q++) s += p[q];
        g_spool[j] = s * (1.f / 16.f);
    }
}

// ------------- K2: merged dw-GEMM (blocks 0..1023) + pointwise heads -------
__global__ void __launch_bounds__(288) k_heads(const float* __restrict__ dw_w,
                                               const float* __restrict__ dw_b,
                                               const float* __restrict__ pk_w,
                                               const float* __restrict__ pk_b,
                                               const float* __restrict__ pb_w,
                                               const float* __restrict__ pb_b) {
    __shared__ float s_col[9][516];
    int tid = threadIdx.x;
    if (blockIdx.x < 1024) {
        // depthwise-kernel GEMM: 4096x72 per n, k=2048
        int n = blockIdx.x >> 7;
        int ocb = blockIdx.x & 127;
        int oc_l = tid / 9, t = tid % 9;
        int oc = ocb * 32 + oc_l;
        const float* wrow = dw_w + (size_t)oc * 2048;
        ull acc = 0ULL;
        for (int kc = 0; kc < 4; kc++) {
            __syncthreads();
            for (int j = tid; j < 9 * 512; j += 288) {
                int tt = j >> 9, kk = j & 511;
                s_col[tt][kk] = g_colT[(n * 9 + tt) * 2048 + kc * 512 + kk];
            }
            __syncthreads();
            const float* wc = wrow + kc * 512;
#pragma unroll 4
            for (int k = 0; k < 512; k += 4) {
                longlong2 w2 = *(const longlong2*)(wc + k);
                longlong2 c2 = *(const longlong2*)(&s_col[t][k]);
                acc = fma2((ull)w2.x, (ull)c2.x, acc);
                acc = fma2((ull)w2.y, (ull)c2.y, acc);
            }
        }
        float lo, hi;
        unpack2(acc, lo, hi);
        g_dw[((size_t)n * 4096 + oc) * 9 + t] = lo + hi + dw_b[oc];
    } else {
        int idx = (blockIdx.x - 1024) * 288 + tid;
        if (idx < 32768) {
            int n = idx >> 12, oc = idx & 4095;
            const float4* w = (const float4*)(pk_w + (size_t)oc * 512);
            const float4* s = (const float4*)(g_spool + n * 512);
            float acc = pk_b[oc];
#pragma unroll 4
            for (int q = 0; q < 128; q++) {
                float4 a = w[q], b = s[q];
                acc += a.x * b.x + a.y * b.y + a.z * b.z + a.w * b.w;
            }
            g_pwkn[idx] = acc;
        } else if (idx < 32768 + 4096) {
            int j = idx - 32768;
            int n = j >> 9, c = j & 511;
            const float4* w = (const float4*)(pb_w + (size_t)c * 512);
            const float4* s = (const float4*)(g_spool + n * 512);
            float acc = pb_b[c];
#pragma unroll 4
            for (int q = 0; q < 128; q++) {
                float4 a = w[q], b = s[q];
                acc += a.x * b.x + a.y * b.y + a.z * b.z + a.w * b.w;
            }
            g_pwbias[j] = acc;
        }
    }
}

// ------------------------- K3: instance-norm stats -------------------------
__global__ void __launch_bounds__(256) k_stats(const float* __restrict__ pred) {
    int bc = blockIdx.x;  // n*512+c
    const float4* p = (const float4*)(pred + (size_t)bc * 16384);
    int tid = threadIdx.x;
    float s = 0.f, ss = 0.f;
#pragma unroll
    for (int k = 0; k < 16; k++) {
        float4 v = p[tid + k * 256];
        s += v.x + v.y + v.z + v.w;
        ss += v.x * v.x + v.y * v.y + v.z * v.z + v.w * v.w;
    }
#pragma unroll
    for (int o = 16; o; o >>= 1) {
        s += __shfl_xor_sync(~0u, s, o);
        ss += __shfl_xor_sync(~0u, ss, o);
    }
    __shared__ float ws[8], wss[8];
    if ((tid & 31) == 0) { ws[tid >> 5] = s; wss[tid >> 5] = ss; }
    __syncthreads();
    if (tid == 0) {
        float S = 0.f, SS = 0.f;
#pragma unroll
        for (int w = 0; w < 8; w++) { S += ws[w]; SS += wss[w]; }
        float mean = S * (1.f / 16384.f);
        float var = (SS - S * mean) * (1.f / 16383.f);  // ddof=1
        g_mean[bc] = mean;
        g_rstd[bc] = rsqrtf(var + 1e-5f);
    }
}

// ------------------------- K4: main grouped conv ---------------------------
// grid: (8 tiles [2x x 4y], 512 (n,g)), block 128 threads, dynamic smem.
// Tile: 64 x 32 output; each thread: 8 px x 2 rows x 8 oc (2 passes of 4 oc).
// Per (i,ky): 12 weight LDS.64 feed 96 fma2 (1:8); P-packs reused by 2 rows.
struct ConvSmem {
    float in[8][34][68];     // padded rows: 68*4 = 272B, 16B aligned
    float2 w2[8][8][9];      // fused+scaled weights [o][i][t] duplicated
    float dw[64][9];
    float kn[64];
    float bias[8];
};

__global__ void __launch_bounds__(128) k_conv(const float* __restrict__ pred,
                                              float* __restrict__ out) {
    extern __shared__ ConvSmem sm[];
    ConvSmem& S = sm[0];

    int gb = blockIdx.y;  // n*64+g
    int n = gb >> 6, g = gb & 63;
    int x0 = (blockIdx.x & 1) * 64;
    int y0 = (blockIdx.x >> 1) * 32;
    int tid = threadIdx.x;
    int cbase = n * 512 + g * 8;

    // stage 1: group dw + pwkn
    for (int idx = tid; idx < 576; idx += 128) {
        int t = idx % 9;
        int r = idx / 9;  // j*8+i
        S.dw[r][t] = g_dw[((size_t)n * 4096 + (g * 8 + (r >> 3)) * 8 + (r & 7)) * 9 + t];
    }
    if (tid < 64)
        S.kn[tid] = g_pwkn[n * 4096 + (g * 8 + (tid >> 3)) * 8 + (tid & 7)];
    __syncthreads();

    // stage 2: fuse W_eff * rstd_i; load input tile with reflect halo
    for (int idx = tid; idx < 576; idx += 128) {
        int t = idx % 9;
        int r = idx / 9;
        int i = r & 7;
        int o = r >> 3;
        float acc = 0.f;
#pragma unroll
        for (int j = 0; j < 8; j++) acc += S.kn[o * 8 + j] * S.dw[j * 8 + i][t];
        float w = acc * g_rstd[cbase + i];
        S.w2[o][i][t] = make_float2(w, w);
    }
    const float* pbase = pred + (size_t)cbase * 16384;
    for (int idx = tid; idx < 8 * 34 * 66; idx += 128) {
        int rx = idx % 66;
        int r = idx / 66;
        int ry = r % 34;
        int i = r / 34;
        int gy = y0 - 1 + ry;
        gy = gy < 0 ? -gy : (gy > 127 ? 254 - gy : gy);
        int gx = x0 - 1 + rx;
        gx = gx < 0 ? -gx : (gx > 127 ? 254 - gx : gx);
        S.in[i][ry][rx] = pbase[(size_t)i * 16384 + gy * 128 + gx];
    }
    __syncthreads();

    // stage 3: bias with mean fold
    if (tid < 8) {
        int o = tid;
        float b = g_pwbias[cbase + o];
#pragma unroll
        for (int i = 0; i < 8; i++) {
            float m = g_mean[cbase + i];
            float sw = 0.f;
#pragma unroll
            for (int t = 0; t < 9; t++) sw += S.w2[o][i][t].x;
            b -= sw * m;
        }
        S.bias[o] = b;
    }
    __syncthreads();

    int px = tid & 7;   // x octet (8 output pixels)
    int ty = tid >> 3;  // 0..15 -> output rows 2ty, 2ty+1 (tile-local)
    int r0 = ty * 2;

#pragma unroll 1
    for (int oh = 0; oh < 2; oh++) {
        ull acc[4][2][4];  // [o][row][pair]
#pragma unroll
        for (int o = 0; o < 4; o++)
#pragma unroll
            for (int r = 0; r < 2; r++)
#pragma unroll
                for (int q = 0; q < 4; q++) acc[o][r][q] = 0ULL;

#pragma unroll 1
        for (int i = 0; i < 8; i++) {
#pragma unroll
            for (int ky = 0; ky < 3; ky++) {
                // input rows for out-row0 (l0) and out-row1 (l0+1) at this ky
                const float* rp0 = &S.in[i][r0 + ky][px * 8];
                const float* rp1 = &S.in[i][r0 + ky + 1][px * 8];
                float4 a0 = *(const float4*)rp0;
                float4 b0 = *(const float4*)(rp0 + 4);
                float v80 = rp0[8], v90 = rp0[9];
                float4 a1 = *(const float4*)rp1;
                float4 b1 = *(const float4*)(rp1 + 4);
                float v81 = rp1[8], v91 = rp1[9];
                ull P0[9], P1[9];
                P0[0] = pack2(a0.x, a0.y); P0[1] = pack2(a0.y, a0.z);
                P0[2] = pack2(a0.z, a0.w); P0[3] = pack2(a0.w, b0.x);
                P0[4] = pack2(b0.x, b0.y); P0[5] = pack2(b0.y, b0.z);
                P0[6] = pack2(b0.z, b0.w); P0[7] = pack2(b0.w, v80);
                P0[8] = pack2(v80, v90);
                P1[0] = pack2(a1.x, a1.y); P1[1] = pack2(a1.y, a1.z);
                P1[2] = pack2(a1.z, a1.w); P1[3] = pack2(a1.w, b1.x);
                P1[4] = pack2(b1.x, b1.y); P1[5] = pack2(b1.y, b1.z);
                P1[6] = pack2(b1.z, b1.w); P1[7] = pack2(b1.w, v81);
                P1[8] = pack2(v81, v91);
#pragma unroll
                for (int kx = 0; kx < 3; kx++) {
#pragma unroll
                    for (int o = 0; o < 4; o++) {
                        ull w2 = *(const ull*)&S.w2[oh * 4 + o][i][ky * 3 + kx];
                        acc[o][0][0] = fma2(w2, P0[kx + 0], acc[o][0][0]);
                        acc[o][0][1] = fma2(w2, P0[kx + 2], acc[o][0][1]);
                        acc[o][0][2] = fma2(w2, P0[kx + 4], acc[o][0][2]);
                        acc[o][0][3] = fma2(w2, P0[kx + 6], acc[o][0][3]);
                        acc[o][1][0] = fma2(w2, P1[kx + 0], acc[o][1][0]);
                        acc[o][1][1] = fma2(w2, P1[kx + 2], acc[o][1][1]);
                        acc[o][1][2] = fma2(w2, P1[kx + 4], acc[o][1][2]);
                        acc[o][1][3] = fma2(w2, P1[kx + 6], acc[o][1][3]);
                    }
                }
            }
        }

#pragma unroll
        for (int o = 0; o < 4; o++) {
            float b = S.bias[oh * 4 + o];
#pragma unroll
            for (int r = 0; r < 2; r++) {
                float u0, u1, u2, u3, u4, u5, u6, u7;
                unpack2(acc[o][r][0], u0, u1);
                unpack2(acc[o][r][1], u2, u3);
                unpack2(acc[o][r][2], u4, u5);
                unpack2(acc[o][r][3], u6, u7);
                float4 lo = make_float4(u0 + b, u1 + b, u2 + b, u3 + b);
                float4 hi = make_float4(u4 + b, u5 + b, u6 + b, u7 + b);
                float* op = out + (size_t)(cbase + oh * 4 + o) * 16384 +
                            (size_t)(y0 + r0 + r) * 128 + x0 + px * 8;
                *(float4*)op = lo;
                *(float4*)(op + 4) = hi;
            }
        }
    }
}

// ------------------------- launch ------------------------------------------
extern "C" void kernel_launch(void* const* d_in, const int* in_sizes, int n_in,
                              void* d_out, int out_size) {
    const float* style = (const float*)d_in[0];
    const float* predicted = (const float*)d_in[1];
    const float* dw_w = (const float*)d_in[2];
    const float* dw_b = (const float*)d_in[3];
    const float* pk_w = (const float*)d_in[4];
    const float* pk_b = (const float*)d_in[5];
    const float* pb_w = (const float*)d_in[6];
    const float* pb_b = (const float*)d_in[7];
    float* out = (float*)d_out;

    (void)in_sizes; (void)n_in; (void)out_size;

    cudaFuncSetAttribute(k_conv, cudaFuncAttributeMaxDynamicSharedMemorySize,
                         (int)sizeof(ConvSmem));

    k_prep1<<<(147456 + 4096 + 255) / 256, 256>>>(style);
    k_heads<<<1024 + 128, 288>>>(dw_w, dw_b, pk_w, pk_b, pb_w, pb_b);
    k_stats<<<4096, 256>>>(predicted);
    dim3 cgrid(8, 512);
    k_conv<<<cgrid, 128, sizeof(ConvSmem)>>>(predicted, out);
}